// round 4
// baseline (speedup 1.0000x reference)
#include <cuda_runtime.h>

static constexpr int NMAX = 8192;
static constexpr float CC = 5.0e-7f;   // 1/(2*1000^2)
static constexpr int NB = 148;
static constexpr int NT = 512;
static constexpr int NTH = NB * NT;    // 75776 threads

// Scratch (device globals — no allocation allowed)
__device__ float  g_deg[NMAX];
__device__ float  g_dinv[NMAX];
__device__ float4 g_geom[NMAX];              // {px, py, r, -}
__device__ float4 g_U[NMAX];                 // {u0, u1, ux, uy}
__device__ __align__(16) float g_S[768];     // S1(4*64) | S2(4*32) | S3(4*32)
__device__ unsigned g_arr;                   // barrier arrive counter
__device__ unsigned g_gen;                   // barrier generation

__device__ __forceinline__ void redv4(float* p, float a, float b, float c, float d) {
    asm volatile("red.global.add.v4.f32 [%0], {%1,%2,%3,%4};"
                 :: "l"(p), "f"(a), "f"(b), "f"(c), "f"(d) : "memory");
}
__device__ __forceinline__ void redf(float* p, float v) {
    asm volatile("red.global.add.f32 [%0], %1;" :: "l"(p), "f"(v) : "memory");
}

// Software grid barrier (all NB blocks co-resident by construction).
__device__ __forceinline__ void gridbar() {
    __syncthreads();
    if (threadIdx.x == 0) {
        __threadfence();
        unsigned gen = *(volatile unsigned*)&g_gen;
        if (atomicAdd(&g_arr, 1u) == NB - 1u) {
            atomicExch(&g_arr, 0u);
            __threadfence();
            atomicAdd(&g_gen, 1u);                 // release
        } else {
            while (*(volatile unsigned*)&g_gen == gen) __nanosleep(32);
            __threadfence();                        // acquire
        }
    }
    __syncthreads();
}

// Block-redundant tiny GEMV: shT[q*Cout+c] = sum_k S[q*Cin+k] * W[k*Cout+c]
__device__ __forceinline__ void project_sh(const float* S, const float* __restrict__ W,
                                           int Cin, int Cout, float* shT) {
    int t = threadIdx.x;
    if (t < 4 * Cout) {
        int row = t / Cout, c = t - row * Cout;
        float acc = 0.f;
        for (int k = 0; k < Cin; k++) acc += S[row * Cin + k] * W[k * Cout + c];
        shT[row * Cout + c] = acc;
    }
    __syncthreads();
}

__device__ __forceinline__ float4 node_coeffs(float4 ge, float di, float4 u) {
    float di2 = di * di;
    float4 a;
    a.x = di * (u.x - CC * u.y) + di2 * (1.0f - CC * ge.z);   // * T0
    a.y = -CC * (di * u.x + di2);                             // * T1
    a.z = 2.0f * CC * (di * u.z + di2 * ge.x);                // * T2x
    a.w = 2.0f * CC * (di * u.w + di2 * ge.y);                // * T2y
    return a;
}

// Shared-memory cross-row reduce of 4 accumulators, then red.v4 into Sout.
template <int G, int RPB>
__device__ __forceinline__ void block_reduce_emit(float4 s0, float4 s1, float4 s2, float4 s3,
                                                  float4* sm, float* Sout, int C) {
    int t = threadIdx.x, g = t % G, rl = t / G;
    sm[t * 4 + 0] = s0; sm[t * 4 + 1] = s1; sm[t * 4 + 2] = s2; sm[t * 4 + 3] = s3;
    __syncthreads();
    for (int s = RPB / 2; s >= 1; s >>= 1) {
        if (rl < s) {
            int o = (t + s * G) * 4;
#pragma unroll
            for (int q = 0; q < 4; q++) {
                float4 a = sm[t * 4 + q], b = sm[o + q];
                a.x += b.x; a.y += b.y; a.z += b.z; a.w += b.w;
                sm[t * 4 + q] = a;
            }
        }
        __syncthreads();
    }
    if (rl == 0) {
#pragma unroll
        for (int q = 0; q < 4; q++) {
            float4 v = sm[t * 4 + q];
            redv4(&Sout[q * C + 4 * g], v.x, v.y, v.z, v.w);
        }
    }
    __syncthreads();
}

__global__ void __launch_bounds__(NT)
k_fused(const float* __restrict__ x, const float* __restrict__ pos,
        const int* __restrict__ ei,
        const float* __restrict__ W1, const float* __restrict__ b1,
        const float* __restrict__ W2, const float* __restrict__ b2,
        const float* __restrict__ W3, const float* __restrict__ b3,
        float* __restrict__ out, int n, int E) {
    __shared__ float  shT[256];
    __shared__ float4 sm[NT * 4];
    int tid = threadIdx.x;
    int gt = blockIdx.x * NT + tid;

    int nE4 = E >> 2;
    int erem = E & 3, ebase = E & ~3;

    // ---- Phase A: deg=1 (self-loop), S=0 ----
    for (int i = gt; i < n; i += NTH) g_deg[i] = 1.0f;
    if (gt < 768) g_S[gt] = 0.0f;
    gridbar();

    // ---- Phase B: deg count (4-wide, single shot) + geom/U init + S1 reduce ----
    if (gt < nE4) {
        int4 d4 = reinterpret_cast<const int4*>(ei + E)[gt];
        redf(&g_deg[d4.x], 1.0f); redf(&g_deg[d4.y], 1.0f);
        redf(&g_deg[d4.z], 1.0f); redf(&g_deg[d4.w], 1.0f);
    }
    if (gt < erem) redf(&g_deg[ei[E + ebase + gt]], 1.0f);
    for (int i = gt; i < n; i += NTH) {
        float2 p = reinterpret_cast<const float2*>(pos)[i];
        g_geom[i] = make_float4(p.x, p.y, p.x * p.x + p.y * p.y, 0.f);
        g_U[i] = make_float4(0.f, 0.f, 0.f, 0.f);
    }
    {
        constexpr int C = 64, G = 16, RPB = NT / G;
        int g = tid % G, rl = tid / G;
        float4 s0 = {0,0,0,0}, s1 = {0,0,0,0}, s2 = {0,0,0,0}, s3 = {0,0,0,0};
        for (int i0 = blockIdx.x * RPB; i0 < n; i0 += NB * RPB) {
            int i = i0 + rl;
            if (i < n) {
                float4 v = *reinterpret_cast<const float4*>(&x[i * C + 4 * g]);
                float2 p = reinterpret_cast<const float2*>(pos)[i];
                float r = p.x * p.x + p.y * p.y;
                s0.x += v.x;       s0.y += v.y;       s0.z += v.z;       s0.w += v.w;
                s1.x += r * v.x;   s1.y += r * v.y;   s1.z += r * v.z;   s1.w += r * v.w;
                s2.x += p.x * v.x; s2.y += p.x * v.y; s2.z += p.x * v.z; s2.w += p.x * v.w;
                s3.x += p.y * v.x; s3.y += p.y * v.y; s3.z += p.y * v.z; s3.w += p.y * v.w;
            }
        }
        block_reduce_emit<G, RPB>(s0, s1, s2, s3, sm, g_S, C);
    }
    gridbar();

    // ---- Phase C: U scatter (4-wide, single shot) + dinv cache ----
    if (gt < nE4) {
        int4 s4 = reinterpret_cast<const int4*>(ei)[gt];
        int4 d4 = reinterpret_cast<const int4*>(ei + E)[gt];
        float4 ga = g_geom[s4.x], gb = g_geom[s4.y], gc = g_geom[s4.z], gd = g_geom[s4.w];
        float da = g_deg[s4.x], db = g_deg[s4.y], dc = g_deg[s4.z], dd = g_deg[s4.w];
        float ia = rsqrtf(da), ib = rsqrtf(db), ic = rsqrtf(dc), id = rsqrtf(dd);
        redv4(reinterpret_cast<float*>(&g_U[d4.x]), ia, ia * ga.z, ia * ga.x, ia * ga.y);
        redv4(reinterpret_cast<float*>(&g_U[d4.y]), ib, ib * gb.z, ib * gb.x, ib * gb.y);
        redv4(reinterpret_cast<float*>(&g_U[d4.z]), ic, ic * gc.z, ic * gc.x, ic * gc.y);
        redv4(reinterpret_cast<float*>(&g_U[d4.w]), id, id * gd.z, id * gd.x, id * gd.y);
    }
    if (gt < erem) {
        int s = ei[ebase + gt], d = ei[E + ebase + gt];
        float4 ge = g_geom[s];
        float di = rsqrtf(g_deg[s]);
        redv4(reinterpret_cast<float*>(&g_U[d]), di, di * ge.z, di * ge.x, di * ge.y);
    }
    for (int i = gt; i < n; i += NTH) g_dinv[i] = rsqrtf(g_deg[i]);
    gridbar();

    // ---- Phases D/E: T = S@W (block-redundant), combine+relu, reduce -> next S ----
    const float* Ws[2] = {W1, W2};
    const float* bs[2] = {b1, b2};
    for (int layer = 0; layer < 2; layer++) {
        project_sh(layer == 0 ? g_S : g_S + 256, Ws[layer], layer == 0 ? 64 : 32, 32, shT);
        constexpr int C = 32, G = 8, RPB = NT / G;
        int g = tid % G, rl = tid / G;
        float4 t0 = *reinterpret_cast<const float4*>(&shT[4 * g]);
        float4 t1 = *reinterpret_cast<const float4*>(&shT[C + 4 * g]);
        float4 t2 = *reinterpret_cast<const float4*>(&shT[2 * C + 4 * g]);
        float4 t3 = *reinterpret_cast<const float4*>(&shT[3 * C + 4 * g]);
        float4 bv = *reinterpret_cast<const float4*>(&bs[layer][4 * g]);
        float4 s0 = {0,0,0,0}, s1 = {0,0,0,0}, s2 = {0,0,0,0}, s3 = {0,0,0,0};
        for (int i0 = blockIdx.x * RPB; i0 < n; i0 += NB * RPB) {
            int i = i0 + rl;
            if (i < n) {
                float4 ge = g_geom[i];
                float di = g_dinv[i];
                float4 a = node_coeffs(ge, di, g_U[i]);
                float4 v;
                v.x = fmaxf(a.x * t0.x + a.y * t1.x + a.z * t2.x + a.w * t3.x + bv.x, 0.f);
                v.y = fmaxf(a.x * t0.y + a.y * t1.y + a.z * t2.y + a.w * t3.y + bv.y, 0.f);
                v.z = fmaxf(a.x * t0.z + a.y * t1.z + a.z * t2.z + a.w * t3.z + bv.z, 0.f);
                v.w = fmaxf(a.x * t0.w + a.y * t1.w + a.z * t2.w + a.w * t3.w + bv.w, 0.f);
                s0.x += v.x;        s0.y += v.y;        s0.z += v.z;        s0.w += v.w;
                s1.x += ge.z * v.x; s1.y += ge.z * v.y; s1.z += ge.z * v.z; s1.w += ge.z * v.w;
                s2.x += ge.x * v.x; s2.y += ge.x * v.y; s2.z += ge.x * v.z; s2.w += ge.x * v.w;
                s3.x += ge.y * v.x; s3.y += ge.y * v.y; s3.z += ge.y * v.z; s3.w += ge.y * v.w;
            }
        }
        block_reduce_emit<G, RPB>(s0, s1, s2, s3, sm, layer == 0 ? g_S + 256 : g_S + 384, C);
        gridbar();
    }

    // ---- Phase F: T3 = S3@W3, final combine + log_softmax ----
    project_sh(g_S + 384, W3, 32, 16, shT);
    for (int i = gt; i < n; i += NTH) {
        float4 ge = g_geom[i];
        float di = g_dinv[i];
        float4 a = node_coeffs(ge, di, g_U[i]);
        float v[16];
#pragma unroll
        for (int c = 0; c < 16; c++)
            v[c] = a.x * shT[c] + a.y * shT[16 + c] + a.z * shT[32 + c] + a.w * shT[48 + c]
                 + b3[c];
        float m = v[0];
#pragma unroll
        for (int c = 1; c < 16; c++) m = fmaxf(m, v[c]);
        float s = 0.f;
#pragma unroll
        for (int c = 0; c < 16; c++) s += __expf(v[c] - m);
        float l = m + __logf(s);
        float4* o = reinterpret_cast<float4*>(out + i * 16);
#pragma unroll
        for (int q = 0; q < 4; q++) {
            float4 w;
            w.x = v[4 * q] - l;     w.y = v[4 * q + 1] - l;
            w.z = v[4 * q + 2] - l; w.w = v[4 * q + 3] - l;
            o[q] = w;
        }
    }
}

extern "C" void kernel_launch(void* const* d_in, const int* in_sizes, int n_in,
                              void* d_out, int out_size) {
    const float* x   = (const float*)d_in[0];
    const float* pos = (const float*)d_in[1];
    const int*   ei  = (const int*)d_in[2];
    const float* W1  = (const float*)d_in[3];
    const float* b1  = (const float*)d_in[4];
    const float* W2  = (const float*)d_in[5];
    const float* b2  = (const float*)d_in[6];
    const float* W3  = (const float*)d_in[7];
    const float* b3  = (const float*)d_in[8];
    int n = in_sizes[1] / 2;   // pos is (N,2)
    int E = in_sizes[2] / 2;   // edge_index is (2,E)

    k_fused<<<NB, NT>>>(x, pos, ei, W1, b1, W2, b2, W3, b3, (float*)d_out, n, E);
}

// round 5
// speedup vs baseline: 1.1855x; 1.1855x over previous
#include <cuda_runtime.h>

static constexpr int NMAX = 8192;
static constexpr float CC = 5.0e-7f;   // 1/(2*1000^2)
static constexpr int NB = 148;
static constexpr int NT = 256;
static constexpr int NTH = NB * NT;

// Scratch (device globals, zero-initialized at module load).
// INVARIANT: g_deg, g_U, g_S, g_arr, g_fin are all-zero at kernel entry and
// are restored to zero by the end of every run (see reset points below).
__device__ float  g_deg[NMAX];               // incoming-edge count (self-loop folded as +1 at use)
__device__ float  g_dinv[NMAX];
__device__ float4 g_geom[NMAX];              // {px, py, r, -}
__device__ float4 g_U[NMAX];                 // {u0, u1, ux, uy}
__device__ __align__(16) float g_S[512];     // S1[0,256) | S2[256,384) | S3[384,512)
__device__ unsigned g_arr, g_gen, g_fin;

__device__ __forceinline__ void redv4(float* p, float a, float b, float c, float d) {
    asm volatile("red.global.add.v4.f32 [%0], {%1,%2,%3,%4};"
                 :: "l"(p), "f"(a), "f"(b), "f"(c), "f"(d) : "memory");
}
__device__ __forceinline__ void redf(float* p, float v) {
    asm volatile("red.global.add.f32 [%0], %1;" :: "l"(p), "f"(v) : "memory");
}

// Software grid barrier, tight spin (all NB blocks co-resident by construction).
__device__ __forceinline__ void gridbar() {
    __syncthreads();
    if (threadIdx.x == 0) {
        unsigned gen = *(volatile unsigned*)&g_gen;
        __threadfence();
        if (atomicAdd(&g_arr, 1u) == NB - 1u) {
            g_arr = 0u;
            __threadfence();
            atomicAdd(&g_gen, 1u);                         // release
        } else {
            while (*(volatile unsigned*)&g_gen == gen) {}   // tight spin
            __threadfence();                                // acquire
        }
    }
    __syncthreads();
}

__device__ __forceinline__ float4 node_coeffs(float4 ge, float di, float4 u) {
    float di2 = di * di;
    float4 a;
    a.x = di * (u.x - CC * u.y) + di2 * (1.0f - CC * ge.z);   // * T0
    a.y = -CC * (di * u.x + di2);                             // * T1
    a.z = 2.0f * CC * (di * u.z + di2 * ge.x);                // * T2x
    a.w = 2.0f * CC * (di * u.w + di2 * ge.y);                // * T2y
    return a;
}

// Shared-memory cross-row reduce of 4 accumulators, then red.v4 into Sout.
template <int G, int RPB>
__device__ __forceinline__ void block_reduce_emit(float4 s0, float4 s1, float4 s2, float4 s3,
                                                  float4* sm, float* Sout, int C) {
    int t = threadIdx.x, g = t % G, rl = t / G;
    sm[t * 4 + 0] = s0; sm[t * 4 + 1] = s1; sm[t * 4 + 2] = s2; sm[t * 4 + 3] = s3;
    __syncthreads();
    for (int s = RPB / 2; s >= 1; s >>= 1) {
        if (rl < s) {
            int o = (t + s * G) * 4;
#pragma unroll
            for (int q = 0; q < 4; q++) {
                float4 a = sm[t * 4 + q], b = sm[o + q];
                a.x += b.x; a.y += b.y; a.z += b.z; a.w += b.w;
                sm[t * 4 + q] = a;
            }
        }
        __syncthreads();
    }
    if (rl == 0) {
#pragma unroll
        for (int q = 0; q < 4; q++) {
            float4 v = sm[t * 4 + q];
            redv4(&Sout[q * C + 4 * g], v.x, v.y, v.z, v.w);
        }
    }
    __syncthreads();
}

// Combine layer output (C=32, relu) from shared T + bias, reduce into Sout.
template <bool RESET_DEG>
__device__ __forceinline__ void combine32(const float* shT, const float* __restrict__ bias,
                                          float* Sout, float4* sm, int n) {
    constexpr int C = 32, G = 8, RPB = NT / G;   // RPB = 32
    int tid = threadIdx.x;
    int g = tid % G, rl = tid / G;
    float4 t0 = *reinterpret_cast<const float4*>(&shT[4 * g]);
    float4 t1 = *reinterpret_cast<const float4*>(&shT[C + 4 * g]);
    float4 t2 = *reinterpret_cast<const float4*>(&shT[2 * C + 4 * g]);
    float4 t3 = *reinterpret_cast<const float4*>(&shT[3 * C + 4 * g]);
    float4 bv = *reinterpret_cast<const float4*>(&bias[4 * g]);
    float4 s0 = {0,0,0,0}, s1 = {0,0,0,0}, s2 = {0,0,0,0}, s3 = {0,0,0,0};
    for (int i0 = blockIdx.x * RPB; i0 < n; i0 += NB * RPB) {
        int i = i0 + rl;
        if (i < n) {
            float4 ge = g_geom[i];
            float di = g_dinv[i];
            float4 a = node_coeffs(ge, di, g_U[i]);
            if (RESET_DEG && g == 0) g_deg[i] = 0.0f;   // restore zero-invariant
            float4 v;
            v.x = fmaxf(a.x * t0.x + a.y * t1.x + a.z * t2.x + a.w * t3.x + bv.x, 0.f);
            v.y = fmaxf(a.x * t0.y + a.y * t1.y + a.z * t2.y + a.w * t3.y + bv.y, 0.f);
            v.z = fmaxf(a.x * t0.z + a.y * t1.z + a.z * t2.z + a.w * t3.z + bv.z, 0.f);
            v.w = fmaxf(a.x * t0.w + a.y * t1.w + a.z * t2.w + a.w * t3.w + bv.w, 0.f);
            s0.x += v.x;        s0.y += v.y;        s0.z += v.z;        s0.w += v.w;
            s1.x += ge.z * v.x; s1.y += ge.z * v.y; s1.z += ge.z * v.z; s1.w += ge.z * v.w;
            s2.x += ge.x * v.x; s2.y += ge.x * v.y; s2.z += ge.x * v.z; s2.w += ge.x * v.w;
            s3.x += ge.y * v.x; s3.y += ge.y * v.y; s3.z += ge.y * v.z; s3.w += ge.y * v.w;
        }
    }
    block_reduce_emit<G, RPB>(s0, s1, s2, s3, sm, Sout, C);
}

__global__ void __launch_bounds__(NT)
k_fused(const float* __restrict__ x, const float* __restrict__ pos,
        const int* __restrict__ ei,
        const float* __restrict__ W1, const float* __restrict__ b1,
        const float* __restrict__ W2, const float* __restrict__ b2,
        const float* __restrict__ W3, const float* __restrict__ b3,
        float* __restrict__ out, int n, int E) {
    __shared__ __align__(16) float shT[128];
    __shared__ float4 sm[NT * 4];
    const int tid = threadIdx.x;
    const int gt  = blockIdx.x * NT + tid;
    const int nE4 = E >> 2;
    const int ebase = nE4 << 2;
    const int4* src4 = reinterpret_cast<const int4*>(ei);
    const int4* dst4 = reinterpret_cast<const int4*>(ei + E);

    // ---- Phase 1: deg count (4-wide) + geom + S1 reduce over x ----
    for (int e = gt; e < nE4; e += NTH) {
        int4 d = dst4[e];
        redf(&g_deg[d.x], 1.f); redf(&g_deg[d.y], 1.f);
        redf(&g_deg[d.z], 1.f); redf(&g_deg[d.w], 1.f);
    }
    for (int e = ebase + gt; e < E; e += NTH) redf(&g_deg[ei[E + e]], 1.f);
    for (int i = gt; i < n; i += NTH) {
        float2 p = reinterpret_cast<const float2*>(pos)[i];
        g_geom[i] = make_float4(p.x, p.y, p.x * p.x + p.y * p.y, 0.f);
    }
    {
        constexpr int C = 64, G = 16, RPB = NT / G;   // RPB = 16
        int g = tid % G, rl = tid / G;
        float4 s0 = {0,0,0,0}, s1 = {0,0,0,0}, s2 = {0,0,0,0}, s3 = {0,0,0,0};
        for (int i0 = blockIdx.x * RPB; i0 < n; i0 += NB * RPB) {
            int i = i0 + rl;
            if (i < n) {
                float4 v = *reinterpret_cast<const float4*>(&x[i * C + 4 * g]);
                float2 p = reinterpret_cast<const float2*>(pos)[i];
                float r = p.x * p.x + p.y * p.y;
                s0.x += v.x;       s0.y += v.y;       s0.z += v.z;       s0.w += v.w;
                s1.x += r * v.x;   s1.y += r * v.y;   s1.z += r * v.z;   s1.w += r * v.w;
                s2.x += p.x * v.x; s2.y += p.x * v.y; s2.z += p.x * v.z; s2.w += p.x * v.w;
                s3.x += p.y * v.x; s3.y += p.y * v.y; s3.z += p.y * v.z; s3.w += p.y * v.w;
            }
        }
        block_reduce_emit<G, RPB>(s0, s1, s2, s3, sm, g_S, C);
    }
    gridbar();  // bar1: deg, geom, S1 final

    // ---- Phase 2: U scatter (4-wide) + dinv + project T1 (overlaps drain) ----
    for (int e = gt; e < nE4; e += NTH) {
        int4 s = src4[e];
        int4 d = dst4[e];
        float4 ga = g_geom[s.x], gb = g_geom[s.y], gc = g_geom[s.z], gd = g_geom[s.w];
        float ia = rsqrtf(1.f + g_deg[s.x]), ib = rsqrtf(1.f + g_deg[s.y]);
        float ic = rsqrtf(1.f + g_deg[s.z]), id = rsqrtf(1.f + g_deg[s.w]);
        redv4(reinterpret_cast<float*>(&g_U[d.x]), ia, ia * ga.z, ia * ga.x, ia * ga.y);
        redv4(reinterpret_cast<float*>(&g_U[d.y]), ib, ib * gb.z, ib * gb.x, ib * gb.y);
        redv4(reinterpret_cast<float*>(&g_U[d.z]), ic, ic * gc.z, ic * gc.x, ic * gc.y);
        redv4(reinterpret_cast<float*>(&g_U[d.w]), id, id * gd.z, id * gd.x, id * gd.y);
    }
    for (int e = ebase + gt; e < E; e += NTH) {
        int s = ei[e], d = ei[E + e];
        float4 ge = g_geom[s];
        float di = rsqrtf(1.f + g_deg[s]);
        redv4(reinterpret_cast<float*>(&g_U[d]), di, di * ge.z, di * ge.x, di * ge.y);
    }
    for (int i = gt; i < n; i += NTH) g_dinv[i] = rsqrtf(1.f + g_deg[i]);
    if (tid < 128) {                     // T1 = S1 @ W1  (4x32), overlaps atomic drain
        int row = tid >> 5, c = tid & 31;
        float acc = 0.f;
#pragma unroll 8
        for (int k = 0; k < 64; k++) acc += g_S[row * 64 + k] * W1[k * 32 + c];
        shT[tid] = acc;                  // shT[row*32 + c]
    }
    gridbar();  // bar2: U, dinv, shT(T1) final

    // ---- Phase 3: combine L1 -> S2 ; reset deg & S1 ----
    if (gt < 256) g_S[gt] = 0.f;        // reset S1 (block 0)
    combine32<true>(shT, b1, g_S + 256, sm, n);
    gridbar();  // bar3: S2 final

    // ---- Phase 4: project T2 ; combine L2 -> S3 ----
    if (tid < 128) {
        int row = tid >> 5, c = tid & 31;
        float acc = 0.f;
#pragma unroll
        for (int k = 0; k < 32; k++) acc += g_S[256 + row * 32 + k] * W2[k * 32 + c];
        shT[tid] = acc;
    }
    __syncthreads();
    combine32<false>(shT, b2, g_S + 384, sm, n);
    gridbar();  // bar4: S3 final

    // ---- Phase 5: project T3 ; final + log_softmax ; resets ----
    if (tid < 64) {
        int row = tid >> 4, c = tid & 15;
        float acc = 0.f;
#pragma unroll
        for (int k = 0; k < 32; k++) acc += g_S[384 + row * 32 + k] * W3[k * 16 + c];
        shT[row * 16 + c] = acc;
    }
    if (tid >= 64 && tid < 80) shT[tid] = b3[tid - 64];
    __syncthreads();
    if (tid == 0) {                      // last block past the S3 read zeroes it
        __threadfence();
        if (atomicAdd(&g_fin, 1u) == NB - 1u) {
            for (int k = 384; k < 512; k++) g_S[k] = 0.f;
            g_fin = 0u;
        }
    }
    if (gt < 128) g_S[256 + gt] = 0.f;   // reset S2 (block 0)
    for (int i = gt; i < n; i += NTH) {
        float4 ge = g_geom[i];
        float di = g_dinv[i];
        float4 u = g_U[i];
        g_U[i] = make_float4(0.f, 0.f, 0.f, 0.f);   // restore zero-invariant
        float4 a = node_coeffs(ge, di, u);
        float v[16];
#pragma unroll
        for (int c = 0; c < 16; c++)
            v[c] = a.x * shT[c] + a.y * shT[16 + c] + a.z * shT[32 + c] + a.w * shT[48 + c]
                 + shT[64 + c];
        float m = v[0];
#pragma unroll
        for (int c = 1; c < 16; c++) m = fmaxf(m, v[c]);
        float s = 0.f;
#pragma unroll
        for (int c = 0; c < 16; c++) s += __expf(v[c] - m);
        float l = m + __logf(s);
        float4* o = reinterpret_cast<float4*>(out + i * 16);
#pragma unroll
        for (int q = 0; q < 4; q++) {
            float4 w;
            w.x = v[4 * q] - l;     w.y = v[4 * q + 1] - l;
            w.z = v[4 * q + 2] - l; w.w = v[4 * q + 3] - l;
            o[q] = w;
        }
    }
}

extern "C" void kernel_launch(void* const* d_in, const int* in_sizes, int n_in,
                              void* d_out, int out_size) {
    const float* x   = (const float*)d_in[0];
    const float* pos = (const float*)d_in[1];
    const int*   ei  = (const int*)d_in[2];
    const float* W1  = (const float*)d_in[3];
    const float* b1  = (const float*)d_in[4];
    const float* W2  = (const float*)d_in[5];
    const float* b2  = (const float*)d_in[6];
    const float* W3  = (const float*)d_in[7];
    const float* b3  = (const float*)d_in[8];
    int n = in_sizes[1] / 2;   // pos is (N,2)
    int E = in_sizes[2] / 2;   // edge_index is (2,E)

    k_fused<<<NB, NT>>>(x, pos, ei, W1, b1, W2, b2, W3, b3, (float*)d_out, n, E);
}